// round 2
// baseline (speedup 1.0000x reference)
#include <cuda_runtime.h>
#include <math.h>

#define NB   8
#define TT   2048
#define DD   1024
#define MTOT (NB * TT)   // 16384

#define BM 128
#define BN 128
#define BK 16
#define PAD 4

// Scratch (allocation-free rule: __device__ globals)
__device__ float g_q[(size_t)MTOT * DD];
__device__ float g_k[(size_t)MTOT * DD];
__device__ float g_v[(size_t)MTOT * DD];
__device__ float g_temp[MTOT];
__device__ float g_scores[(size_t)NB * TT * TT];

// ---------------------------------------------------------------------------
// Generic tiled GEMM.
//   BT=true :  C = A * B^T   (A: MxK row-major, B: NxK row-major)
//   BT=false:  C = A * B     (A: MxK row-major, B: KxN row-major)
// Optional per-row scale in epilogue (for temp * scores).
// Batched via blockIdx.z with element strides sA/sB/sC/sScale.
// M % 128 == 0, N % 128 == 0, K % 16 == 0 assumed (true for all uses here).
// ---------------------------------------------------------------------------
template <bool BT>
__global__ __launch_bounds__(256, 2)
void gemm_kernel(const float* __restrict__ A, const float* __restrict__ Bm,
                 float* __restrict__ C, int M, int N, int K,
                 size_t sA, size_t sB, size_t sC,
                 const float* __restrict__ rowscale, int sScale)
{
    __shared__ float As[BK][BM + PAD];
    __shared__ float Bs[BK][BN + PAD];

    const int z = blockIdx.z;
    A  += (size_t)z * sA;
    Bm += (size_t)z * sB;
    C  += (size_t)z * sC;
    if (rowscale) rowscale += (size_t)z * sScale;

    const int tid  = threadIdx.x;
    const int row0 = blockIdx.y * BM;
    const int col0 = blockIdx.x * BN;
    const int tm   = tid / 16;   // 0..15
    const int tn   = tid % 16;   // 0..15

    float acc[8][8];
#pragma unroll
    for (int i = 0; i < 8; i++)
#pragma unroll
        for (int j = 0; j < 8; j++) acc[i][j] = 0.0f;

    for (int k0 = 0; k0 < K; k0 += BK) {
        // ---- load A tile (transposed into As[k][m]) ----
#pragma unroll
        for (int t = tid; t < 512; t += 256) {
            int i = t >> 2, j4 = t & 3;
            float4 a = *(const float4*)(A + (size_t)(row0 + i) * K + k0 + j4 * 4);
            As[j4 * 4 + 0][i] = a.x;
            As[j4 * 4 + 1][i] = a.y;
            As[j4 * 4 + 2][i] = a.z;
            As[j4 * 4 + 3][i] = a.w;
        }
        // ---- load B tile ----
        if (BT) {
#pragma unroll
            for (int t = tid; t < 512; t += 256) {
                int i = t >> 2, j4 = t & 3;
                float4 b = *(const float4*)(Bm + (size_t)(col0 + i) * K + k0 + j4 * 4);
                Bs[j4 * 4 + 0][i] = b.x;
                Bs[j4 * 4 + 1][i] = b.y;
                Bs[j4 * 4 + 2][i] = b.z;
                Bs[j4 * 4 + 3][i] = b.w;
            }
        } else {
#pragma unroll
            for (int t = tid; t < 512; t += 256) {
                int j = t >> 5, i4 = t & 31;
                float4 b = *(const float4*)(Bm + (size_t)(k0 + j) * N + col0 + i4 * 4);
                *(float4*)&Bs[j][i4 * 4] = b;
            }
        }
        __syncthreads();

#pragma unroll
        for (int kk = 0; kk < BK; kk++) {
            float4 a0 = *(const float4*)&As[kk][tm * 4];
            float4 a1 = *(const float4*)&As[kk][tm * 4 + 64];
            float4 b0 = *(const float4*)&Bs[kk][tn * 4];
            float4 b1 = *(const float4*)&Bs[kk][tn * 4 + 64];
            float ar[8] = {a0.x, a0.y, a0.z, a0.w, a1.x, a1.y, a1.z, a1.w};
            float br[8] = {b0.x, b0.y, b0.z, b0.w, b1.x, b1.y, b1.z, b1.w};
#pragma unroll
            for (int i = 0; i < 8; i++)
#pragma unroll
                for (int j = 0; j < 8; j++)
                    acc[i][j] += ar[i] * br[j];
        }
        __syncthreads();
    }

    // ---- epilogue ----
#pragma unroll
    for (int i = 0; i < 8; i++) {
        int m = row0 + tm * 4 + (i & 3) + (i >> 2) * 64;
        float s = 1.0f;
        if (rowscale) s = rowscale[m];
        float4 o0 = make_float4(acc[i][0] * s, acc[i][1] * s, acc[i][2] * s, acc[i][3] * s);
        float4 o1 = make_float4(acc[i][4] * s, acc[i][5] * s, acc[i][6] * s, acc[i][7] * s);
        *(float4*)(C + (size_t)m * N + col0 + tn * 4)      = o0;
        *(float4*)(C + (size_t)m * N + col0 + tn * 4 + 64) = o1;
    }
}

// ---------------------------------------------------------------------------
// Reductions
// ---------------------------------------------------------------------------
__device__ __forceinline__ float warp_sum(float v) {
#pragma unroll
    for (int o = 16; o > 0; o >>= 1) v += __shfl_xor_sync(0xffffffffu, v, o);
    return v;
}
__device__ __forceinline__ float warp_max(float v) {
#pragma unroll
    for (int o = 16; o > 0; o >>= 1) v = fmaxf(v, __shfl_xor_sync(0xffffffffu, v, o));
    return v;
}

// ---------------------------------------------------------------------------
// temp[row] = clip(hbar / (||q_row|| + eps), 0.1, 5.0)   (one block per row)
// ---------------------------------------------------------------------------
__global__ void temp_kernel(const float* __restrict__ q,
                            const float* __restrict__ hbar,
                            float* __restrict__ temp)
{
    int row = blockIdx.x;
    const float4* qr = (const float4*)(q + (size_t)row * DD);
    int tid = threadIdx.x;                   // 256 threads, D/4 = 256 float4s
    float4 a = qr[tid];
    float s = a.x * a.x + a.y * a.y + a.z * a.z + a.w * a.w;
    s = warp_sum(s);
    __shared__ float red[8];
    if ((tid & 31) == 0) red[tid >> 5] = s;
    __syncthreads();
    if (tid == 0) {
        float t = 0.0f;
#pragma unroll
        for (int i = 0; i < 8; i++) t += red[i];
        float n  = sqrtf(t);
        float tv = hbar[0] / (n + 1e-8f);
        tv = fminf(fmaxf(tv, 0.1f), 5.0f);
        temp[row] = tv;
    }
}

// ---------------------------------------------------------------------------
// In-place row softmax over TT=2048 columns (one block of 256 per row)
// ---------------------------------------------------------------------------
__global__ void softmax_kernel(float* __restrict__ sc)
{
    size_t row = blockIdx.x;
    float* p = sc + row * (size_t)TT;
    int tid = threadIdx.x;

    float v[8];
    float mx = -3.4e38f;
#pragma unroll
    for (int j = 0; j < 8; j++) {
        v[j] = p[tid + j * 256];
        mx = fmaxf(mx, v[j]);
    }
    mx = warp_max(mx);
    __shared__ float red[8];
    __shared__ float bval;
    if ((tid & 31) == 0) red[tid >> 5] = mx;
    __syncthreads();
    if (tid == 0) {
        float m = red[0];
#pragma unroll
        for (int i = 1; i < 8; i++) m = fmaxf(m, red[i]);
        bval = m;
    }
    __syncthreads();
    mx = bval;

    float s = 0.0f;
#pragma unroll
    for (int j = 0; j < 8; j++) {
        v[j] = expf(v[j] - mx);
        s += v[j];
    }
    s = warp_sum(s);
    __syncthreads();   // red[] reuse: ensure all max-phase reads done
    if ((tid & 31) == 0) red[tid >> 5] = s;
    __syncthreads();
    if (tid == 0) {
        float t = 0.0f;
#pragma unroll
        for (int i = 0; i < 8; i++) t += red[i];
        bval = t;
    }
    __syncthreads();
    float inv = 1.0f / bval;
#pragma unroll
    for (int j = 0; j < 8; j++) p[tid + j * 256] = v[j] * inv;
}

// ---------------------------------------------------------------------------
extern "C" void kernel_launch(void* const* d_in, const int* in_sizes, int n_in,
                              void* d_out, int out_size)
{
    const float* x  = (const float*)d_in[0];
    const float* Wq = (const float*)d_in[1];
    const float* Wk = (const float*)d_in[2];
    const float* Wv = (const float*)d_in[3];
    const float* hb = (const float*)d_in[4];
    float* out = (float*)d_out;

    float *q, *k, *v, *tmp, *sc;
    cudaGetSymbolAddress((void**)&q,   g_q);
    cudaGetSymbolAddress((void**)&k,   g_k);
    cudaGetSymbolAddress((void**)&v,   g_v);
    cudaGetSymbolAddress((void**)&tmp, g_temp);
    cudaGetSymbolAddress((void**)&sc,  g_scores);

    dim3 blk(256);

    // 1) QKV projections:  C[m,e] = sum_d x[m,d] * W[e,d]  ->  A * B^T
    dim3 g_qkv(DD / BN, MTOT / BM, 1);
    gemm_kernel<true><<<g_qkv, blk>>>(x, Wq, q, MTOT, DD, DD, 0, 0, 0, nullptr, 0);
    gemm_kernel<true><<<g_qkv, blk>>>(x, Wk, k, MTOT, DD, DD, 0, 0, 0, nullptr, 0);
    gemm_kernel<true><<<g_qkv, blk>>>(x, Wv, v, MTOT, DD, DD, 0, 0, 0, nullptr, 0);

    // 2) per-query adaptive temperature
    temp_kernel<<<MTOT, 256>>>(q, hb, tmp);

    // 3) scores = (q @ k^T) * temp[row]   batched over NB
    dim3 g_sc(TT / BN, TT / BM, NB);
    gemm_kernel<true><<<g_sc, blk>>>(q, k, sc, TT, TT, DD,
                                     (size_t)TT * DD, (size_t)TT * DD,
                                     (size_t)TT * TT, tmp, TT);

    // 4) row softmax
    softmax_kernel<<<MTOT, 256>>>(sc);

    // 5) out = attn @ v   batched over NB  (A * B form)
    dim3 g_out(DD / BN, TT / BM, NB);
    gemm_kernel<false><<<g_out, blk>>>(sc, v, out, TT, DD, TT,
                                       (size_t)TT * TT, (size_t)TT * DD,
                                       (size_t)TT * DD, nullptr, 0);
}

// round 4
// speedup vs baseline: 2.3101x; 2.3101x over previous
#include <cuda_runtime.h>
#include <cuda_bf16.h>
#include <math.h>
#include <stdint.h>

#define NB 8
#define TT 2048
#define DD 1024
#define MTOT (NB*TT)

#define BM 128
#define BN 128
#define BKE 32
#define STAGES 3
#define STG_BYTES 32768          // Ah 8K | Al 8K | Bh 8K | Bl 8K
#define SMEM_SZ (STAGES*STG_BYTES)

__device__ __nv_bfloat16 g_xhi[(size_t)MTOT*DD], g_xlo[(size_t)MTOT*DD];
__device__ __nv_bfloat16 g_wqhi[DD*DD], g_wqlo[DD*DD];
__device__ __nv_bfloat16 g_wkhi[DD*DD], g_wklo[DD*DD];
__device__ __nv_bfloat16 g_wvhi[DD*DD], g_wvlo[DD*DD];
__device__ __nv_bfloat16 g_qhi[(size_t)MTOT*DD], g_qlo[(size_t)MTOT*DD];
__device__ __nv_bfloat16 g_khi[(size_t)MTOT*DD], g_klo[(size_t)MTOT*DD];
__device__ __nv_bfloat16 g_vthi[(size_t)MTOT*DD], g_vtlo[(size_t)MTOT*DD];   // [DD][MTOT]
__device__ __nv_bfloat16 g_ahi[(size_t)NB*TT*TT], g_alo[(size_t)NB*TT*TT];
__device__ float g_sc[(size_t)NB*TT*TT];
__device__ float g_temp[MTOT];

// ------------------------- helpers -------------------------
__device__ __forceinline__ uint32_t smem_u32(const void* p) {
    uint32_t a;
    asm("{ .reg .u64 t; cvta.to.shared.u64 t, %1; cvt.u32.u64 %0, t; }" : "=r"(a) : "l"(p));
    return a;
}
__device__ __forceinline__ void cp16(uint32_t dst, const void* src) {
    asm volatile("cp.async.cg.shared.global [%0], [%1], 16;" :: "r"(dst), "l"(src));
}
__device__ __forceinline__ void ldsm4(uint32_t* r, uint32_t a) {
    asm volatile("ldmatrix.sync.aligned.m8n8.x4.shared.b16 {%0,%1,%2,%3}, [%4];"
                 : "=r"(r[0]), "=r"(r[1]), "=r"(r[2]), "=r"(r[3]) : "r"(a));
}
__device__ __forceinline__ void mma16816(float* c, const uint32_t* a, const uint32_t* b) {
    asm volatile("mma.sync.aligned.m16n8k16.row.col.f32.bf16.bf16.f32 "
                 "{%0,%1,%2,%3}, {%4,%5,%6,%7}, {%8,%9}, {%0,%1,%2,%3};"
                 : "+f"(c[0]), "+f"(c[1]), "+f"(c[2]), "+f"(c[3])
                 : "r"(a[0]), "r"(a[1]), "r"(a[2]), "r"(a[3]), "r"(b[0]), "r"(b[1]));
}
// 16B-chunk XOR swizzle: row r (0..127), chunk c (0..3); 64B rows
__device__ __forceinline__ uint32_t swoff(int r, int c) {
    return (uint32_t)((r * 4 + (c ^ ((r >> 1) & 3))) << 4);
}
__device__ __forceinline__ uint32_t pack2(__nv_bfloat16 a, __nv_bfloat16 b) {
    __nv_bfloat162 t(a, b);
    return *(uint32_t*)&t;
}
__device__ __forceinline__ void split1(float f, __nv_bfloat16& h, __nv_bfloat16& l) {
    h = __float2bfloat16(f);
    l = __float2bfloat16(f - __bfloat162float(h));
}

// ---------------------------------------------------------------------------
// bf16x3 HMMA GEMM: C = A * B^T  (A: MxK, B: NxK, K-major hi/lo pairs)
// MODE 0: C hi/lo bf16 row-major       MODE 1: C hi/lo bf16 transposed [n][m]
// MODE 2: C fp32 * rowscale[row]       MODE 3: C fp32
// ---------------------------------------------------------------------------
template <int MODE>
__global__ __launch_bounds__(256, 1)
void gemm3_kernel(const __nv_bfloat16* __restrict__ Ahi, const __nv_bfloat16* __restrict__ Alo,
                  const __nv_bfloat16* __restrict__ Bhi, const __nv_bfloat16* __restrict__ Blo,
                  float* __restrict__ Cf, __nv_bfloat16* __restrict__ Chi, __nv_bfloat16* __restrict__ Clo,
                  int K, int lda, int ldb, int ldc,
                  size_t sA, size_t sB, size_t sC, const float* __restrict__ rowscale)
{
    extern __shared__ char sm[];
    const uint32_t sbase = smem_u32(sm);
    const int tid = threadIdx.x, lane = tid & 31, wid = tid >> 5;
    const int wm = wid >> 2, wn = wid & 3;            // 2 x 4 warp grid
    const int m0 = blockIdx.y * BM, n0 = blockIdx.x * BN, z = blockIdx.z;

    Ahi += (size_t)z * sA;  Alo += (size_t)z * sA;
    Bhi += (size_t)z * sB;  Blo += (size_t)z * sB;

    const int KT = K / BKE;

    auto load = [&](int kt) {
        const uint32_t st = sbase + (uint32_t)(kt % STAGES) * STG_BYTES;
        const int k0 = kt * BKE;
#pragma unroll
        for (int i = 0; i < 2; i++) {
            const int id = tid + i * 256;             // 0..511
            const int r = id >> 2, c = id & 3;
            const uint32_t so = swoff(r, c);
            const size_t ga = (size_t)(m0 + r) * lda + k0 + c * 8;
            const size_t gb = (size_t)(n0 + r) * ldb + k0 + c * 8;
            cp16(st + so,         Ahi + ga);
            cp16(st + 8192 + so,  Alo + ga);
            cp16(st + 16384 + so, Bhi + gb);
            cp16(st + 24576 + so, Blo + gb);
        }
        asm volatile("cp.async.commit_group;");
    };

    float acc[4][4][4];
#pragma unroll
    for (int f = 0; f < 4; f++)
#pragma unroll
        for (int g = 0; g < 4; g++)
#pragma unroll
            for (int p = 0; p < 4; p++) acc[f][g][p] = 0.0f;

    // ldmatrix lane address components
    const int rA = (lane & 7) + ((lane >> 3) & 1) * 8;   // A: +8 on bit3, k-half on bit4
    const int cA = lane >> 4;
    const int rB = (lane & 7) + ((lane >> 4) & 1) * 8;   // B: +8 on bit4, k-half on bit3
    const int cB = (lane >> 3) & 1;

    load(0); load(1);

    for (int kt = 0; kt < KT; kt++) {
        if (kt == KT - 1) asm volatile("cp.async.wait_group 0;");
        else              asm volatile("cp.async.wait_group 1;");
        __syncthreads();
        if (kt + 2 < KT) load(kt + 2);

        const uint32_t st = sbase + (uint32_t)(kt % STAGES) * STG_BYTES;
#pragma unroll
        for (int k16 = 0; k16 < 2; k16++) {
            uint32_t bh[8], bl[8];
#pragma unroll
            for (int g2 = 0; g2 < 2; g2++) {
                const int r = wn * 32 + g2 * 16 + rB;
                const uint32_t ad = st + 16384 + swoff(r, k16 * 2 + cB);
                ldsm4(&bh[g2 * 4], ad);
                ldsm4(&bl[g2 * 4], ad + 8192);
            }
#pragma unroll
            for (int f = 0; f < 4; f++) {
                uint32_t ah[4], al[4];
                const int r = wm * 64 + f * 16 + rA;
                const uint32_t ad = st + swoff(r, k16 * 2 + cA);
                ldsm4(ah, ad);
                ldsm4(al, ad + 8192);
#pragma unroll
                for (int g = 0; g < 4; g++) {
                    mma16816(acc[f][g], ah, &bh[g * 2]);
                    mma16816(acc[f][g], ah, &bl[g * 2]);
                    mma16816(acc[f][g], al, &bh[g * 2]);
                }
            }
        }
    }

    // -------------------------- epilogue --------------------------
    if (MODE == 0) {
#pragma unroll
        for (int f = 0; f < 4; f++) {
            const int r1 = m0 + wm * 64 + f * 16 + (lane >> 2);
            const int r2 = r1 + 8;
#pragma unroll
            for (int g = 0; g < 4; g++) {
                const int col = n0 + wn * 32 + g * 8 + (lane & 3) * 2;
                __nv_bfloat16 h0, l0, h1, l1;
                split1(acc[f][g][0], h0, l0); split1(acc[f][g][1], h1, l1);
                *(uint32_t*)(Chi + (size_t)r1 * ldc + col) = pack2(h0, h1);
                *(uint32_t*)(Clo + (size_t)r1 * ldc + col) = pack2(l0, l1);
                split1(acc[f][g][2], h0, l0); split1(acc[f][g][3], h1, l1);
                *(uint32_t*)(Chi + (size_t)r2 * ldc + col) = pack2(h0, h1);
                *(uint32_t*)(Clo + (size_t)r2 * ldc + col) = pack2(l0, l1);
            }
        }
    } else if (MODE == 1) {
        __syncthreads();    // stage buffers reused for transpose
        float* ws = (float*)(sm + wid * 8448);       // [64][33]
#pragma unroll
        for (int f = 0; f < 4; f++)
#pragma unroll
            for (int g = 0; g < 4; g++) {
                const int mm = f * 16 + (lane >> 2);
                const int nn = g * 8 + (lane & 3) * 2;
                ws[mm * 33 + nn]           = acc[f][g][0];
                ws[mm * 33 + nn + 1]       = acc[f][g][1];
                ws[(mm + 8) * 33 + nn]     = acc[f][g][2];
                ws[(mm + 8) * 33 + nn + 1] = acc[f][g][3];
            }
        __syncwarp();
        const int nrow = n0 + wn * 32 + lane;
        __nv_bfloat16* ph = Chi + (size_t)nrow * ldc + m0 + wm * 64;
        __nv_bfloat16* pl = Clo + (size_t)nrow * ldc + m0 + wm * 64;
#pragma unroll
        for (int q4 = 0; q4 < 8; q4++) {
            uint32_t hv[2], lv[2];
#pragma unroll
            for (int p = 0; p < 2; p++) {
                __nv_bfloat16 h0, l0, h1, l1;
                split1(ws[(q4 * 8 + p * 4 + 0) * 33 + lane], h0, l0);
                split1(ws[(q4 * 8 + p * 4 + 1) * 33 + lane], h1, l1);
                __nv_bfloat16 h2, l2, h3, l3;
                split1(ws[(q4 * 8 + p * 4 + 2) * 33 + lane], h2, l2);
                split1(ws[(q4 * 8 + p * 4 + 3) * 33 + lane], h3, l3);
                hv[p] = pack2(h0, h1); lv[p] = pack2(l0, l1);
                ((uint32_t*)(ph + q4 * 8))[p * 2]     = hv[p];
                ((uint32_t*)(ph + q4 * 8))[p * 2 + 1] = pack2(h2, h3);
                ((uint32_t*)(pl + q4 * 8))[p * 2]     = lv[p];
                ((uint32_t*)(pl + q4 * 8))[p * 2 + 1] = pack2(l2, l3);
            }
        }
    } else {
        float* C0 = Cf + (size_t)z * sC;
#pragma unroll
        for (int f = 0; f < 4; f++) {
            const int r1 = m0 + wm * 64 + f * 16 + (lane >> 2);
            const int r2 = r1 + 8;
            float s1 = 1.0f, s2 = 1.0f;
            if (MODE == 2) {
                s1 = rowscale[(size_t)z * TT + r1];
                s2 = rowscale[(size_t)z * TT + r2];
            }
#pragma unroll
            for (int g = 0; g < 4; g++) {
                const int col = n0 + wn * 32 + g * 8 + (lane & 3) * 2;
                *(float2*)(C0 + (size_t)r1 * ldc + col) = make_float2(acc[f][g][0] * s1, acc[f][g][1] * s1);
                *(float2*)(C0 + (size_t)r2 * ldc + col) = make_float2(acc[f][g][2] * s2, acc[f][g][3] * s2);
            }
        }
    }
}

// ------------------------- aux kernels -------------------------
__global__ void split_kernel(const float* __restrict__ x, __nv_bfloat16* __restrict__ hi,
                             __nv_bfloat16* __restrict__ lo, size_t n4)
{
    size_t i = (size_t)blockIdx.x * blockDim.x + threadIdx.x;
    if (i >= n4) return;
    float4 v = ((const float4*)x)[i];
    __nv_bfloat16 h0,l0,h1,l1,h2,l2,h3,l3;
    split1(v.x,h0,l0); split1(v.y,h1,l1); split1(v.z,h2,l2); split1(v.w,h3,l3);
    ((uint2*)hi)[i] = make_uint2(pack2(h0,h1), pack2(h2,h3));
    ((uint2*)lo)[i] = make_uint2(pack2(l0,l1), pack2(l2,l3));
}

__device__ __forceinline__ float warp_sum(float v) {
#pragma unroll
    for (int o = 16; o > 0; o >>= 1) v += __shfl_xor_sync(0xffffffffu, v, o);
    return v;
}
__device__ __forceinline__ float warp_max(float v) {
#pragma unroll
    for (int o = 16; o > 0; o >>= 1) v = fmaxf(v, __shfl_xor_sync(0xffffffffu, v, o));
    return v;
}

__global__ void temp_kernel(const __nv_bfloat16* __restrict__ qhi, const __nv_bfloat16* __restrict__ qlo,
                            const float* __restrict__ hbar, float* __restrict__ temp)
{
    int row = blockIdx.x, tid = threadIdx.x;
    size_t base = (size_t)row * DD + tid * 4;
    uint2 h = *(const uint2*)(qhi + base), l = *(const uint2*)(qlo + base);
    __nv_bfloat162 h0 = *(__nv_bfloat162*)&h.x, h1 = *(__nv_bfloat162*)&h.y;
    __nv_bfloat162 l0 = *(__nv_bfloat162*)&l.x, l1 = *(__nv_bfloat162*)&l.y;
    float a = __bfloat162float(h0.x) + __bfloat162float(l0.x);
    float b = __bfloat162float(h0.y) + __bfloat162float(l0.y);
    float c = __bfloat162float(h1.x) + __bfloat162float(l1.x);
    float d = __bfloat162float(h1.y) + __bfloat162float(l1.y);
    float s = warp_sum(a*a + b*b + c*c + d*d);
    __shared__ float red[8];
    if ((tid & 31) == 0) red[tid >> 5] = s;
    __syncthreads();
    if (tid == 0) {
        float t = 0.0f;
#pragma unroll
        for (int i = 0; i < 8; i++) t += red[i];
        float tv = hbar[0] / (sqrtf(t) + 1e-8f);
        temp[row] = fminf(fmaxf(tv, 0.1f), 5.0f);
    }
}

__global__ void softmax_kernel(const float* __restrict__ sc, __nv_bfloat16* __restrict__ ahi,
                               __nv_bfloat16* __restrict__ alo)
{
    size_t row = blockIdx.x;
    const float* p = sc + row * (size_t)TT;
    int tid = threadIdx.x;
    float v[8], mx = -3.4e38f;
#pragma unroll
    for (int j = 0; j < 8; j++) { v[j] = p[tid + j * 256]; mx = fmaxf(mx, v[j]); }
    mx = warp_max(mx);
    __shared__ float red[8];
    __shared__ float bval;
    if ((tid & 31) == 0) red[tid >> 5] = mx;
    __syncthreads();
    if (tid == 0) {
        float m = red[0];
#pragma unroll
        for (int i = 1; i < 8; i++) m = fmaxf(m, red[i]);
        bval = m;
    }
    __syncthreads();
    mx = bval;
    float s = 0.0f;
#pragma unroll
    for (int j = 0; j < 8; j++) { v[j] = expf(v[j] - mx); s += v[j]; }
    s = warp_sum(s);
    __syncthreads();
    if ((tid & 31) == 0) red[tid >> 5] = s;
    __syncthreads();
    if (tid == 0) {
        float t = 0.0f;
#pragma unroll
        for (int i = 0; i < 8; i++) t += red[i];
        bval = t;
    }
    __syncthreads();
    float inv = 1.0f / bval;
#pragma unroll
    for (int j = 0; j < 8; j++) {
        __nv_bfloat16 h, l;
        split1(v[j] * inv, h, l);
        size_t idx = row * (size_t)TT + tid + j * 256;
        ahi[idx] = h;  alo[idx] = l;
    }
}

// ---------------------------------------------------------------------------
extern "C" void kernel_launch(void* const* d_in, const int* in_sizes, int n_in,
                              void* d_out, int out_size)
{
    const float* x  = (const float*)d_in[0];
    const float* Wq = (const float*)d_in[1];
    const float* Wk = (const float*)d_in[2];
    const float* Wv = (const float*)d_in[3];
    const float* hb = (const float*)d_in[4];
    float* out = (float*)d_out;

    __nv_bfloat16 *xhi,*xlo,*wqh,*wql,*wkh,*wkl,*wvh,*wvl,*qhi,*qlo,*khi,*klo,*vth,*vtl,*ahi,*alo;
    float *sc, *tmp;
    cudaGetSymbolAddress((void**)&xhi, g_xhi);  cudaGetSymbolAddress((void**)&xlo, g_xlo);
    cudaGetSymbolAddress((void**)&wqh, g_wqhi); cudaGetSymbolAddress((void**)&wql, g_wqlo);
    cudaGetSymbolAddress((void**)&wkh, g_wkhi); cudaGetSymbolAddress((void**)&wkl, g_wklo);
    cudaGetSymbolAddress((void**)&wvh, g_wvhi); cudaGetSymbolAddress((void**)&wvl, g_wvlo);
    cudaGetSymbolAddress((void**)&qhi, g_qhi);  cudaGetSymbolAddress((void**)&qlo, g_qlo);
    cudaGetSymbolAddress((void**)&khi, g_khi);  cudaGetSymbolAddress((void**)&klo, g_klo);
    cudaGetSymbolAddress((void**)&vth, g_vthi); cudaGetSymbolAddress((void**)&vtl, g_vtlo);
    cudaGetSymbolAddress((void**)&ahi, g_ahi);  cudaGetSymbolAddress((void**)&alo, g_alo);
    cudaGetSymbolAddress((void**)&sc,  g_sc);   cudaGetSymbolAddress((void**)&tmp, g_temp);

    cudaFuncSetAttribute(gemm3_kernel<0>, cudaFuncAttributeMaxDynamicSharedMemorySize, SMEM_SZ);
    cudaFuncSetAttribute(gemm3_kernel<1>, cudaFuncAttributeMaxDynamicSharedMemorySize, SMEM_SZ);
    cudaFuncSetAttribute(gemm3_kernel<2>, cudaFuncAttributeMaxDynamicSharedMemorySize, SMEM_SZ);
    cudaFuncSetAttribute(gemm3_kernel<3>, cudaFuncAttributeMaxDynamicSharedMemorySize, SMEM_SZ);

    // 1) splits
    split_kernel<<<(size_t)MTOT*DD/4/256, 256>>>(x, xhi, xlo, (size_t)MTOT*DD/4);
    split_kernel<<<DD*DD/4/256, 256>>>(Wq, wqh, wql, DD*DD/4);
    split_kernel<<<DD*DD/4/256, 256>>>(Wk, wkh, wkl, DD*DD/4);
    split_kernel<<<DD*DD/4/256, 256>>>(Wv, wvh, wvl, DD*DD/4);

    // 2) projections
    dim3 gq(DD/BN, MTOT/BM, 1);
    gemm3_kernel<0><<<gq, 256, SMEM_SZ>>>(xhi, xlo, wqh, wql, nullptr, qhi, qlo,
                                          DD, DD, DD, DD, 0, 0, 0, nullptr);
    gemm3_kernel<0><<<gq, 256, SMEM_SZ>>>(xhi, xlo, wkh, wkl, nullptr, khi, klo,
                                          DD, DD, DD, DD, 0, 0, 0, nullptr);
    gemm3_kernel<1><<<gq, 256, SMEM_SZ>>>(xhi, xlo, wvh, wvl, nullptr, vth, vtl,
                                          DD, DD, DD, MTOT, 0, 0, 0, nullptr);

    // 3) temp
    temp_kernel<<<MTOT, 256>>>(qhi, qlo, hb, tmp);

    // 4) scores = (q@k^T) * temp
    dim3 gs(TT/BN, TT/BM, NB);
    gemm3_kernel<2><<<gs, 256, SMEM_SZ>>>(qhi, qlo, khi, klo, sc, nullptr, nullptr,
                                          DD, DD, DD, TT,
                                          (size_t)TT*DD, (size_t)TT*DD, (size_t)TT*TT, tmp);

    // 5) softmax -> attn hi/lo
    softmax_kernel<<<MTOT, 256>>>(sc, ahi, alo);

    // 6) out = attn @ v
    dim3 go(DD/BN, TT/BM, NB);
    gemm3_kernel<3><<<go, 256, SMEM_SZ>>>(ahi, alo, vth, vtl, out, nullptr, nullptr,
                                          TT, TT, MTOT, DD,
                                          (size_t)TT*TT, TT, (size_t)TT*DD, nullptr);
}

// round 5
// speedup vs baseline: 2.6966x; 1.1673x over previous
#include <cuda_runtime.h>
#include <cuda_bf16.h>
#include <math.h>
#include <stdint.h>

#define NB 8
#define TT 2048
#define DD 1024
#define MTOT (NB*TT)

#define BM 128
#define BN 128
#define BKE 32
#define STAGES 3
#define STG_BYTES 32768          // Ah 8K | Al 8K | Bh 8K | Bl 8K
#define SMEM_SZ (STAGES*STG_BYTES)

__device__ __nv_bfloat16 g_xhi[(size_t)MTOT*DD], g_xlo[(size_t)MTOT*DD];
__device__ __nv_bfloat16 g_wqhi[DD*DD], g_wqlo[DD*DD];
__device__ __nv_bfloat16 g_wkhi[DD*DD], g_wklo[DD*DD];
__device__ __nv_bfloat16 g_wvhi[DD*DD], g_wvlo[DD*DD];
__device__ __nv_bfloat16 g_qhi[(size_t)MTOT*DD], g_qlo[(size_t)MTOT*DD];
__device__ __nv_bfloat16 g_khi[(size_t)MTOT*DD], g_klo[(size_t)MTOT*DD];
__device__ __nv_bfloat16 g_vthi[(size_t)MTOT*DD], g_vtlo[(size_t)MTOT*DD];   // [DD][MTOT]
__device__ __nv_bfloat16 g_ahi[(size_t)NB*TT*TT], g_alo[(size_t)NB*TT*TT];
__device__ float g_sc[(size_t)NB*TT*TT];
__device__ float g_temp[MTOT];

// ------------------------- helpers -------------------------
__device__ __forceinline__ uint32_t smem_u32(const void* p) {
    uint32_t a;
    asm("{ .reg .u64 t; cvta.to.shared.u64 t, %1; cvt.u32.u64 %0, t; }" : "=r"(a) : "l"(p));
    return a;
}
__device__ __forceinline__ void cp16(uint32_t dst, const void* src) {
    asm volatile("cp.async.cg.shared.global [%0], [%1], 16;" :: "r"(dst), "l"(src));
}
__device__ __forceinline__ void ldsm4(uint32_t* r, uint32_t a) {
    asm volatile("ldmatrix.sync.aligned.m8n8.x4.shared.b16 {%0,%1,%2,%3}, [%4];"
                 : "=r"(r[0]), "=r"(r[1]), "=r"(r[2]), "=r"(r[3]) : "r"(a));
}
__device__ __forceinline__ void mma16816(float* c, const uint32_t* a, const uint32_t* b) {
    asm volatile("mma.sync.aligned.m16n8k16.row.col.f32.bf16.bf16.f32 "
                 "{%0,%1,%2,%3}, {%4,%5,%6,%7}, {%8,%9}, {%0,%1,%2,%3};"
                 : "+f"(c[0]), "+f"(c[1]), "+f"(c[2]), "+f"(c[3])
                 : "r"(a[0]), "r"(a[1]), "r"(a[2]), "r"(a[3]), "r"(b[0]), "r"(b[1]));
}
// 16B-chunk XOR swizzle: row r (0..127), chunk c (0..3); 64B rows
__device__ __forceinline__ uint32_t swoff(int r, int c) {
    return (uint32_t)((r * 4 + (c ^ ((r >> 1) & 3))) << 4);
}
__device__ __forceinline__ uint32_t pack2(__nv_bfloat16 a, __nv_bfloat16 b) {
    __nv_bfloat162 t(a, b);
    return *(uint32_t*)&t;
}
__device__ __forceinline__ void split1(float f, __nv_bfloat16& h, __nv_bfloat16& l) {
    h = __float2bfloat16(f);
    l = __float2bfloat16(f - __bfloat162float(h));
}

// ---------------------------------------------------------------------------
// bf16x3 HMMA GEMM: C = A * B^T  (A: MxK, B: NxK, K-major hi/lo pairs)
// MODE 0: C hi/lo bf16 row-major       MODE 1: C hi/lo bf16 transposed [n][m]
// MODE 2: C fp32 * rowscale[row]       MODE 3: C fp32
// ---------------------------------------------------------------------------
template <int MODE>
__global__ __launch_bounds__(256, 2)
void gemm3_kernel(const __nv_bfloat16* __restrict__ Ahi, const __nv_bfloat16* __restrict__ Alo,
                  const __nv_bfloat16* __restrict__ Bhi, const __nv_bfloat16* __restrict__ Blo,
                  float* __restrict__ Cf, __nv_bfloat16* __restrict__ Chi, __nv_bfloat16* __restrict__ Clo,
                  int K, int lda, int ldb, int ldc,
                  size_t sA, size_t sB, size_t sC, const float* __restrict__ rowscale)
{
    extern __shared__ char sm[];
    const uint32_t sbase = smem_u32(sm);
    const int tid = threadIdx.x, lane = tid & 31, wid = tid >> 5;
    const int wm = wid >> 2, wn = wid & 3;            // 2 x 4 warp grid
    const int m0 = blockIdx.y * BM, n0 = blockIdx.x * BN, z = blockIdx.z;

    Ahi += (size_t)z * sA;  Alo += (size_t)z * sA;
    Bhi += (size_t)z * sB;  Blo += (size_t)z * sB;

    const int KT = K / BKE;

    auto load = [&](int kt) {
        const uint32_t st = sbase + (uint32_t)(kt % STAGES) * STG_BYTES;
        const int k0 = kt * BKE;
#pragma unroll
        for (int i = 0; i < 2; i++) {
            const int id = tid + i * 256;             // 0..511
            const int r = id >> 2, c = id & 3;
            const uint32_t so = swoff(r, c);
            const size_t ga = (size_t)(m0 + r) * lda + k0 + c * 8;
            const size_t gb = (size_t)(n0 + r) * ldb + k0 + c * 8;
            cp16(st + so,         Ahi + ga);
            cp16(st + 8192 + so,  Alo + ga);
            cp16(st + 16384 + so, Bhi + gb);
            cp16(st + 24576 + so, Blo + gb);
        }
        asm volatile("cp.async.commit_group;");
    };

    float acc[4][4][4];
#pragma unroll
    for (int f = 0; f < 4; f++)
#pragma unroll
        for (int g = 0; g < 4; g++)
#pragma unroll
            for (int p = 0; p < 4; p++) acc[f][g][p] = 0.0f;

    // ldmatrix lane address components
    const int rA = (lane & 7) + ((lane >> 3) & 1) * 8;
    const int cA = lane >> 4;
    const int rB = (lane & 7) + ((lane >> 4) & 1) * 8;
    const int cB = (lane >> 3) & 1;

    load(0); load(1);

    for (int kt = 0; kt < KT; kt++) {
        if (kt == KT - 1) asm volatile("cp.async.wait_group 0;");
        else              asm volatile("cp.async.wait_group 1;");
        __syncthreads();
        if (kt + 2 < KT) load(kt + 2);

        const uint32_t st = sbase + (uint32_t)(kt % STAGES) * STG_BYTES;
#pragma unroll
        for (int k16 = 0; k16 < 2; k16++) {
            uint32_t bh[8], bl[8];
#pragma unroll
            for (int g2 = 0; g2 < 2; g2++) {
                const int r = wn * 32 + g2 * 16 + rB;
                const uint32_t ad = st + 16384 + swoff(r, k16 * 2 + cB);
                ldsm4(&bh[g2 * 4], ad);
                ldsm4(&bl[g2 * 4], ad + 8192);
            }
#pragma unroll
            for (int f = 0; f < 4; f++) {
                uint32_t ah[4], al[4];
                const int r = wm * 64 + f * 16 + rA;
                const uint32_t ad = st + swoff(r, k16 * 2 + cA);
                ldsm4(ah, ad);
                ldsm4(al, ad + 8192);
#pragma unroll
                for (int g = 0; g < 4; g++) {
                    mma16816(acc[f][g], ah, &bh[g * 2]);
                    mma16816(acc[f][g], ah, &bl[g * 2]);
                    mma16816(acc[f][g], al, &bh[g * 2]);
                }
            }
        }
    }

    // -------------------------- epilogue --------------------------
    if (MODE == 0) {
#pragma unroll
        for (int f = 0; f < 4; f++) {
            const int r1 = m0 + wm * 64 + f * 16 + (lane >> 2);
            const int r2 = r1 + 8;
#pragma unroll
            for (int g = 0; g < 4; g++) {
                const int col = n0 + wn * 32 + g * 8 + (lane & 3) * 2;
                __nv_bfloat16 h0, l0, h1, l1;
                split1(acc[f][g][0], h0, l0); split1(acc[f][g][1], h1, l1);
                *(uint32_t*)(Chi + (size_t)r1 * ldc + col) = pack2(h0, h1);
                *(uint32_t*)(Clo + (size_t)r1 * ldc + col) = pack2(l0, l1);
                split1(acc[f][g][2], h0, l0); split1(acc[f][g][3], h1, l1);
                *(uint32_t*)(Chi + (size_t)r2 * ldc + col) = pack2(h0, h1);
                *(uint32_t*)(Clo + (size_t)r2 * ldc + col) = pack2(l0, l1);
            }
        }
    } else if (MODE == 1) {
        __syncthreads();    // stage buffers reused for transpose
        float* ws = (float*)(sm + wid * 8448);       // [64][33]
#pragma unroll
        for (int f = 0; f < 4; f++)
#pragma unroll
            for (int g = 0; g < 4; g++) {
                const int mm = f * 16 + (lane >> 2);
                const int nn = g * 8 + (lane & 3) * 2;
                ws[mm * 33 + nn]           = acc[f][g][0];
                ws[mm * 33 + nn + 1]       = acc[f][g][1];
                ws[(mm + 8) * 33 + nn]     = acc[f][g][2];
                ws[(mm + 8) * 33 + nn + 1] = acc[f][g][3];
            }
        __syncwarp();
        const int nrow = n0 + wn * 32 + lane;
        __nv_bfloat16* ph = Chi + (size_t)nrow * ldc + m0 + wm * 64;
        __nv_bfloat16* pl = Clo + (size_t)nrow * ldc + m0 + wm * 64;
#pragma unroll
        for (int q4 = 0; q4 < 8; q4++) {
#pragma unroll
            for (int p = 0; p < 2; p++) {
                __nv_bfloat16 h0, l0, h1, l1, h2, l2, h3, l3;
                split1(ws[(q4 * 8 + p * 4 + 0) * 33 + lane], h0, l0);
                split1(ws[(q4 * 8 + p * 4 + 1) * 33 + lane], h1, l1);
                split1(ws[(q4 * 8 + p * 4 + 2) * 33 + lane], h2, l2);
                split1(ws[(q4 * 8 + p * 4 + 3) * 33 + lane], h3, l3);
                ((uint32_t*)(ph + q4 * 8))[p * 2]     = pack2(h0, h1);
                ((uint32_t*)(ph + q4 * 8))[p * 2 + 1] = pack2(h2, h3);
                ((uint32_t*)(pl + q4 * 8))[p * 2]     = pack2(l0, l1);
                ((uint32_t*)(pl + q4 * 8))[p * 2 + 1] = pack2(l2, l3);
            }
        }
    } else {
        float* C0 = Cf + (size_t)z * sC;
#pragma unroll
        for (int f = 0; f < 4; f++) {
            const int r1 = m0 + wm * 64 + f * 16 + (lane >> 2);
            const int r2 = r1 + 8;
            float s1 = 1.0f, s2 = 1.0f;
            if (MODE == 2) {
                s1 = rowscale[(size_t)z * TT + r1];
                s2 = rowscale[(size_t)z * TT + r2];
            }
#pragma unroll
            for (int g = 0; g < 4; g++) {
                const int col = n0 + wn * 32 + g * 8 + (lane & 3) * 2;
                *(float2*)(C0 + (size_t)r1 * ldc + col) = make_float2(acc[f][g][0] * s1, acc[f][g][1] * s1);
                *(float2*)(C0 + (size_t)r2 * ldc + col) = make_float2(acc[f][g][2] * s2, acc[f][g][3] * s2);
            }
        }
    }
}

// ------------------------- aux kernels -------------------------
__global__ void split_kernel(const float* __restrict__ x, __nv_bfloat16* __restrict__ hi,
                             __nv_bfloat16* __restrict__ lo, size_t n4)
{
    size_t i = (size_t)blockIdx.x * blockDim.x + threadIdx.x;
    if (i >= n4) return;
    float4 v = ((const float4*)x)[i];
    __nv_bfloat16 h0,l0,h1,l1,h2,l2,h3,l3;
    split1(v.x,h0,l0); split1(v.y,h1,l1); split1(v.z,h2,l2); split1(v.w,h3,l3);
    ((uint2*)hi)[i] = make_uint2(pack2(h0,h1), pack2(h2,h3));
    ((uint2*)lo)[i] = make_uint2(pack2(l0,l1), pack2(l2,l3));
}

__device__ __forceinline__ float warp_sum(float v) {
#pragma unroll
    for (int o = 16; o > 0; o >>= 1) v += __shfl_xor_sync(0xffffffffu, v, o);
    return v;
}
__device__ __forceinline__ float warp_max(float v) {
#pragma unroll
    for (int o = 16; o > 0; o >>= 1) v = fmaxf(v, __shfl_xor_sync(0xffffffffu, v, o));
    return v;
}

__global__ void temp_kernel(const __nv_bfloat16* __restrict__ qhi, const __nv_bfloat16* __restrict__ qlo,
                            const float* __restrict__ hbar, float* __restrict__ temp)
{
    int row = blockIdx.x, tid = threadIdx.x;
    size_t base = (size_t)row * DD + tid * 4;
    uint2 h = *(const uint2*)(qhi + base), l = *(const uint2*)(qlo + base);
    __nv_bfloat162 h0 = *(__nv_bfloat162*)&h.x, h1 = *(__nv_bfloat162*)&h.y;
    __nv_bfloat162 l0 = *(__nv_bfloat162*)&l.x, l1 = *(__nv_bfloat162*)&l.y;
    float a = __bfloat162float(h0.x) + __bfloat162float(l0.x);
    float b = __bfloat162float(h0.y) + __bfloat162float(l0.y);
    float c = __bfloat162float(h1.x) + __bfloat162float(l1.x);
    float d = __bfloat162float(h1.y) + __bfloat162float(l1.y);
    float s = warp_sum(a*a + b*b + c*c + d*d);
    __shared__ float red[8];
    if ((tid & 31) == 0) red[tid >> 5] = s;
    __syncthreads();
    if (tid == 0) {
        float t = 0.0f;
#pragma unroll
        for (int i = 0; i < 8; i++) t += red[i];
        float tv = hbar[0] / (sqrtf(t) + 1e-8f);
        temp[row] = fminf(fmaxf(tv, 0.1f), 5.0f);
    }
}

__global__ void softmax_kernel(const float* __restrict__ sc, __nv_bfloat16* __restrict__ ahi,
                               __nv_bfloat16* __restrict__ alo)
{
    size_t row = blockIdx.x;
    const float* p = sc + row * (size_t)TT;
    int tid = threadIdx.x;
    float v[8], mx = -3.4e38f;
#pragma unroll
    for (int j = 0; j < 8; j++) { v[j] = p[tid + j * 256]; mx = fmaxf(mx, v[j]); }
    mx = warp_max(mx);
    __shared__ float red[8];
    __shared__ float bval;
    if ((tid & 31) == 0) red[tid >> 5] = mx;
    __syncthreads();
    if (tid == 0) {
        float m = red[0];
#pragma unroll
        for (int i = 1; i < 8; i++) m = fmaxf(m, red[i]);
        bval = m;
    }
    __syncthreads();
    mx = bval;
    float s = 0.0f;
#pragma unroll
    for (int j = 0; j < 8; j++) { v[j] = expf(v[j] - mx); s += v[j]; }
    s = warp_sum(s);
    __syncthreads();
    if ((tid & 31) == 0) red[tid >> 5] = s;
    __syncthreads();
    if (tid == 0) {
        float t = 0.0f;
#pragma unroll
        for (int i = 0; i < 8; i++) t += red[i];
        bval = t;
    }
    __syncthreads();
    float inv = 1.0f / bval;
#pragma unroll
    for (int j = 0; j < 8; j++) {
        __nv_bfloat16 h, l;
        split1(v[j] * inv, h, l);
        size_t idx = row * (size_t)TT + tid + j * 256;
        ahi[idx] = h;  alo[idx] = l;
    }
}

// ---------------------------------------------------------------------------
extern "C" void kernel_launch(void* const* d_in, const int* in_sizes, int n_in,
                              void* d_out, int out_size)
{
    const float* x  = (const float*)d_in[0];
    const float* Wq = (const float*)d_in[1];
    const float* Wk = (const float*)d_in[2];
    const float* Wv = (const float*)d_in[3];
    const float* hb = (const float*)d_in[4];
    float* out = (float*)d_out;

    __nv_bfloat16 *xhi,*xlo,*wqh,*wql,*wkh,*wkl,*wvh,*wvl,*qhi,*qlo,*khi,*klo,*vth,*vtl,*ahi,*alo;
    float *sc, *tmp;
    cudaGetSymbolAddress((void**)&xhi, g_xhi);  cudaGetSymbolAddress((void**)&xlo, g_xlo);
    cudaGetSymbolAddress((void**)&wqh, g_wqhi); cudaGetSymbolAddress((void**)&wql, g_wqlo);
    cudaGetSymbolAddress((void**)&wkh, g_wkhi); cudaGetSymbolAddress((void**)&wkl, g_wklo);
    cudaGetSymbolAddress((void**)&wvh, g_wvhi); cudaGetSymbolAddress((void**)&wvl, g_wvlo);
    cudaGetSymbolAddress((void**)&qhi, g_qhi);  cudaGetSymbolAddress((void**)&qlo, g_qlo);
    cudaGetSymbolAddress((void**)&khi, g_khi);  cudaGetSymbolAddress((void**)&klo, g_klo);
    cudaGetSymbolAddress((void**)&vth, g_vthi); cudaGetSymbolAddress((void**)&vtl, g_vtlo);
    cudaGetSymbolAddress((void**)&ahi, g_ahi);  cudaGetSymbolAddress((void**)&alo, g_alo);
    cudaGetSymbolAddress((void**)&sc,  g_sc);   cudaGetSymbolAddress((void**)&tmp, g_temp);

    cudaFuncSetAttribute(gemm3_kernel<0>, cudaFuncAttributeMaxDynamicSharedMemorySize, SMEM_SZ);
    cudaFuncSetAttribute(gemm3_kernel<1>, cudaFuncAttributeMaxDynamicSharedMemorySize, SMEM_SZ);
    cudaFuncSetAttribute(gemm3_kernel<2>, cudaFuncAttributeMaxDynamicSharedMemorySize, SMEM_SZ);
    cudaFuncSetAttribute(gemm3_kernel<3>, cudaFuncAttributeMaxDynamicSharedMemorySize, SMEM_SZ);

    // 1) splits
    split_kernel<<<(size_t)MTOT*DD/4/256, 256>>>(x, xhi, xlo, (size_t)MTOT*DD/4);
    split_kernel<<<DD*DD/4/256, 256>>>(Wq, wqh, wql, DD*DD/4);
    split_kernel<<<DD*DD/4/256, 256>>>(Wk, wkh, wkl, DD*DD/4);
    split_kernel<<<DD*DD/4/256, 256>>>(Wv, wvh, wvl, DD*DD/4);

    // 2) projections
    dim3 gq(DD/BN, MTOT/BM, 1);
    gemm3_kernel<0><<<gq, 256, SMEM_SZ>>>(xhi, xlo, wqh, wql, nullptr, qhi, qlo,
                                          DD, DD, DD, DD, 0, 0, 0, nullptr);
    gemm3_kernel<0><<<gq, 256, SMEM_SZ>>>(xhi, xlo, wkh, wkl, nullptr, khi, klo,
                                          DD, DD, DD, DD, 0, 0, 0, nullptr);
    gemm3_kernel<1><<<gq, 256, SMEM_SZ>>>(xhi, xlo, wvh, wvl, nullptr, vth, vtl,
                                          DD, DD, DD, MTOT, 0, 0, 0, nullptr);

    // 3) temp
    temp_kernel<<<MTOT, 256>>>(qhi, qlo, hb, tmp);

    // 4) scores = (q@k^T) * temp
    dim3 gs(TT/BN, TT/BM, NB);
    gemm3_kernel<2><<<gs, 256, SMEM_SZ>>>(qhi, qlo, khi, klo, sc, nullptr, nullptr,
                                          DD, DD, DD, TT,
                                          (size_t)TT*DD, (size_t)TT*DD, (size_t)TT*TT, tmp);

    // 5) softmax -> attn hi/lo
    softmax_kernel<<<MTOT, 256>>>(sc, ahi, alo);

    // 6) out = attn @ v
    dim3 go(DD/BN, TT/BM, NB);
    gemm3_kernel<3><<<go, 256, SMEM_SZ>>>(ahi, alo, vth, vtl, out, nullptr, nullptr,
                                          TT, TT, MTOT, DD,
                                          (size_t)TT*TT, TT, (size_t)TT*DD, nullptr);
}